// round 17
// baseline (speedup 1.0000x reference)
#include <cuda_runtime.h>
#include <cuda_bf16.h>
#include <math.h>
#include <stdint.h>

#define BB 2
#define TT 4
#define CIN 128
#define HH 64
#define WW 64
#define DM 256
#define NQ 300
#define NP 8
#define PS 3
#define NL 6
#define HW (HH*WW)          // 4096
#define ROWS (BB*NQ)        // 600
#define RP (BB*NQ*NP)       // 4800
#define KP (PS*PS*DM)       // 2304
#define K3 (3*CIN)          // 384
#define KQ 320              // padded attn K (300 -> 320)
#define SMEM_DYN 73728      // 3*(8KB A + 16KB B)
// k_attn smem: A 32KB + B 64KB + scores 64*320*4 = 80KB
#define ATTN_SMEM (32768 + 65536 + 81920)

typedef __nv_bfloat16 bf16;

// ----------------------------- scratch (device globals) -----------------------------
__device__ bf16  g_St[BB*HW*K3];
__device__ bf16  g_Wf_bf[DM*K3];
__device__ float g_bfv[DM];
__device__ bf16  g_xbf[BB*HW*DM];
__device__ bf16  g_latbf[BB*HW*DM];
__device__ bf16  g_f1bf[BB*HW*DM];
__device__ bf16  g_wsm_bf[DM*KP];
__device__ bf16  g_wlat_bf[DM*DM];
__device__ bf16  g_wr1T[DM*DM];        // [k][o]
__device__ bf16  g_wb1T[DM*DM];        // [k][o]
__device__ bf16  g_Wq_bf[NL*DM*DM];
__device__ bf16  g_Wo_bf[NL*DM*DM];
__device__ bf16  g_Wp2_bf[NL*DM*DM];
__device__ bf16  g_Wp1_bf[NL*DM*KP];
__device__ float g_queries[ROWS*DM];
__device__ bf16  g_q_bf[ROWS*DM];
__device__ float g_boxes[ROWS*4];
__device__ bf16  g_sampled_bf[RP*KP];
__device__ bf16  g_pvm_bf[ROWS*DM];
__device__ bf16  g_kv_bf[ROWS*DM];
__device__ bf16  g_kvt[BB*DM*KQ];      // kv transposed [b][d][q-pad]
__device__ bf16  g_qq_bf[ROWS*DM];
__device__ bf16  g_attn_bf[ROWS*KQ];

// ----------------------------- PTX helpers -----------------------------
__device__ __forceinline__ uint32_t smem_u32(const void* p){
    uint32_t a;
    asm("{ .reg .u64 t; cvta.to.shared.u64 t, %1; cvt.u32.u64 %0, t; }" : "=r"(a) : "l"(p));
    return a;
}
__device__ __forceinline__ void cp_async16z(uint32_t dst, const void* src, uint32_t sz){
    asm volatile("cp.async.cg.shared.global [%0], [%1], 16, %2;" :: "r"(dst), "l"(src), "r"(sz) : "memory");
}
__device__ __forceinline__ void ldm_x4(uint32_t* r, uint32_t addr){
    asm volatile("ldmatrix.sync.aligned.m8n8.x4.shared.b16 {%0,%1,%2,%3}, [%4];"
                 : "=r"(r[0]), "=r"(r[1]), "=r"(r[2]), "=r"(r[3]) : "r"(addr));
}
__device__ __forceinline__ void mma_bf16(float* c, const uint32_t* a, uint32_t b0, uint32_t b1){
    asm volatile("mma.sync.aligned.m16n8k16.row.col.f32.bf16.bf16.f32 "
                 "{%0,%1,%2,%3}, {%4,%5,%6,%7}, {%8,%9}, {%0,%1,%2,%3};"
                 : "+f"(c[0]), "+f"(c[1]), "+f"(c[2]), "+f"(c[3])
                 : "r"(a[0]), "r"(a[1]), "r"(a[2]), "r"(a[3]), "r"(b0), "r"(b1));
}
#define SWZ(off) ((off) ^ (((off) >> 3) & 0x70))

__device__ __forceinline__ float posval(int p, int d){
    int y = p >> 6, x2 = p & 63;
    int c2, coord;
    if (d < 128){ c2 = d; coord = y; } else { c2 = d - 128; coord = x2; }
    int i = c2 >> 1;
    int par = c2 & 1;
    float cn = (float)(coord+1) / (64.0f + 1e-6f) * 6.28318530717958647692f;
    float ex = (float)(2*(i>>1)) / 64.0f;
    float dimt = powf(10000.0f, ex);
    float a = cn / dimt;
    return par ? cosf(a) : sinf(a);
}

// ===================================================================================
// Generic bf16 HMMA NT GEMM, 3-stage cp.async pipeline.
// epmode==1: add sine positional encoding (row=pixel, col=channel), write Cb only.
// Mout!=0  : relu(bias+acc), reduce over 8-row groups, write mean -> Mout (pv+mean fusion).
// ===================================================================================
__global__ void __launch_bounds__(256) k_hmma(
    const bf16* __restrict__ A, const bf16* __restrict__ B,
    const float* __restrict__ biasN, const float* __restrict__ Cres,
    float* __restrict__ Cf, bf16* __restrict__ Cb, bf16* __restrict__ Ct,
    bf16* __restrict__ Mout,
    int M, int N, int K, int lda, int ldb, int ldc,
    long sA, long sB, long sC,
    int act, float alpha, int epmode)
{
    extern __shared__ __align__(128) char smem[];
    const uint32_t sb = smem_u32(smem);
    const int tid = threadIdx.x;
    const int lane = tid & 31, wid = tid >> 5;
    const int warp_m = wid & 1;
    const int warp_n = wid >> 1;
    const int m0 = blockIdx.x * 64;
    const int n0 = blockIdx.y * 128;
    const long zo = blockIdx.z;
    const bf16* Ab = A + zo * sA;
    const bf16* Bb = B + zo * sB;
    const int nit = K >> 6;

    float acc[2][4][4];
    #pragma unroll
    for (int mi=0;mi<2;mi++)
        #pragma unroll
        for (int ni=0;ni<4;ni++)
            #pragma unroll
            for (int c=0;c<4;c++) acc[mi][ni][c]=0.f;

    #define STAGE(IT) do { \
        int kk = (IT) * 64; \
        uint32_t abuf = sb + ((IT)%3)*8192; \
        uint32_t bbuf = sb + 24576 + ((IT)%3)*16384; \
        for (int e = tid; e < 512; e += 256){ \
            int r = e >> 3, c = e & 7; \
            int gm = m0 + r; \
            int rm = gm < M ? gm : 0; \
            uint32_t sz = gm < M ? 16u : 0u; \
            uint32_t off = (uint32_t)(r*128 + c*16); \
            cp_async16z(abuf + SWZ(off), Ab + (size_t)rm*lda + kk + c*8, sz); \
        } \
        for (int e = tid; e < 1024; e += 256){ \
            int r = e >> 3, c = e & 7; \
            int gn = n0 + r; \
            int rn = gn < N ? gn : 0; \
            uint32_t sz = gn < N ? 16u : 0u; \
            uint32_t off = (uint32_t)(r*128 + c*16); \
            cp_async16z(bbuf + SWZ(off), Bb + (size_t)rn*ldb + kk + c*8, sz); \
        } \
        asm volatile("cp.async.commit_group;" ::: "memory"); \
    } while(0)

    STAGE(0);
    if (nit > 1) STAGE(1);
    for (int it = 0; it < nit; it++){
        if (it < nit-1) asm volatile("cp.async.wait_group 1;" ::: "memory");
        else            asm volatile("cp.async.wait_group 0;" ::: "memory");
        __syncthreads();
        if (it + 2 < nit) STAGE(it+2);
        uint32_t abuf = sb + (it%3)*8192;
        uint32_t bbuf = sb + 24576 + (it%3)*16384;
        #pragma unroll
        for (int ks = 0; ks < 4; ks++){
            uint32_t afr[2][4], bfr[2][4];
            #pragma unroll
            for (int mi = 0; mi < 2; mi++){
                int row = warp_m*32 + mi*16 + (lane & 15);
                uint32_t off = (uint32_t)(row*128 + ks*32 + ((lane>>4)<<4));
                ldm_x4(afr[mi], abuf + SWZ(off));
            }
            #pragma unroll
            for (int p = 0; p < 2; p++){
                int row = warp_n*32 + p*16 + (lane & 15);
                uint32_t off = (uint32_t)(row*128 + ks*32 + ((lane>>4)<<4));
                ldm_x4(bfr[p], bbuf + SWZ(off));
            }
            #pragma unroll
            for (int mi = 0; mi < 2; mi++)
                #pragma unroll
                for (int ni = 0; ni < 4; ni++)
                    mma_bf16(acc[mi][ni], afr[mi],
                             bfr[ni>>1][ni&1], bfr[ni>>1][2 + (ni&1)]);
        }
    }
    #undef STAGE

    // ---- mean-fused epilogue (pv path) ----
    if (Mout){
        __syncthreads();                   // all mma reads done before smem reuse
        float* red = (float*)smem;         // [64][132] padded
        #pragma unroll
        for (int ni = 0; ni < 4; ni++){
            int col = warp_n*32 + ni*8 + (lane & 3)*2;  // local col (N=256, full tiles)
            float b0 = biasN[n0+col], b1 = biasN[n0+col+1];
            #pragma unroll
            for (int mi = 0; mi < 2; mi++){
                int rbase = warp_m*32 + mi*16 + (lane >> 2);
                #pragma unroll
                for (int h = 0; h < 2; h++){
                    int row = rbase + h*8;
                    red[row*132 + col]     = fmaxf(acc[mi][ni][h*2+0]*alpha + b0, 0.f);
                    red[row*132 + col + 1] = fmaxf(acc[mi][ni][h*2+1]*alpha + b1, 0.f);
                }
            }
        }
        __syncthreads();
        for (int e = tid; e < 1024; e += 256){
            int g = e >> 7, c = e & 127;
            float s = 0.f;
            #pragma unroll
            for (int j = 0; j < 8; j++) s += red[(g*8+j)*132 + c];
            Mout[(size_t)((m0>>3) + g)*DM + n0 + c] = __float2bfloat16(s * 0.125f);
        }
        return;
    }

    // ---- standard epilogue ----
    #pragma unroll
    for (int ni = 0; ni < 4; ni++){
        int col = n0 + warp_n*32 + ni*8 + (lane & 3)*2;
        bool cok = col < N;
        float b0 = (cok && biasN) ? biasN[col]   : 0.f;
        float b1 = (cok && biasN) ? biasN[col+1] : 0.f;
        #pragma unroll
        for (int mi = 0; mi < 2; mi++){
            int rbase = m0 + warp_m*32 + mi*16 + (lane >> 2);
            #pragma unroll
            for (int h = 0; h < 2; h++){
                int row = rbase + h*8;
                if (row >= M || !cok) continue;
                float v0 = acc[mi][ni][h*2+0]*alpha + b0;
                float v1 = acc[mi][ni][h*2+1]*alpha + b1;
                long ci = zo*sC + (long)row*ldc + col;
                if (epmode == 1){
                    Cb[ci]   = __float2bfloat16(v0 + posval(row, col));
                    Cb[ci+1] = __float2bfloat16(v1 + posval(row, col+1));
                    continue;
                }
                if (Cres){ v0 += Cres[ci]; v1 += Cres[ci+1]; }
                if (act){ v0 = fmaxf(v0, 0.f); v1 = fmaxf(v1, 0.f); }
                if (Cf){ Cf[ci] = v0; Cf[ci+1] = v1; }
                if (Cb){ Cb[ci] = __float2bfloat16(v0); Cb[ci+1] = __float2bfloat16(v1); }
                if (Ct){
                    int bq = row / NQ, q = row % NQ;
                    long t0 = (long)bq*DM*KQ + (long)col*KQ + q;
                    Ct[t0]      = __float2bfloat16(v0);
                    Ct[t0 + KQ] = __float2bfloat16(v1);
                }
            }
        }
    }
}

// ===================================================================================
// conv3x3 im2col HMMA, 3-stage. M=BB*HW, N=256, K=2304.
// ===================================================================================
__global__ void __launch_bounds__(256) k_conv_hmma(
    const bf16* __restrict__ latbf, const bf16* __restrict__ Wt,
    const float* __restrict__ biasN, bf16* __restrict__ outbf)
{
    extern __shared__ __align__(128) char smem[];
    const uint32_t sb = smem_u32(smem);
    const int tid = threadIdx.x;
    const int lane = tid & 31, wid = tid >> 5;
    const int warp_m = wid & 1;
    const int warp_n = wid >> 1;
    const int m0 = blockIdx.x * 64;
    const int n0 = blockIdx.y * 128;
    const int bimg = m0 >> 12;
    const int yimg = (m0 >> 6) & 63;
    const int nit = KP >> 6;   // 36

    float acc[2][4][4];
    #pragma unroll
    for (int mi=0;mi<2;mi++)
        #pragma unroll
        for (int ni=0;ni<4;ni++)
            #pragma unroll
            for (int c=0;c<4;c++) acc[mi][ni][c]=0.f;

    #define CSTAGE(IT) do { \
        int kk = (IT) * 64; \
        int tap = kk >> 8; \
        int kc  = kk & 255; \
        int dy = tap/3 - 1, dx = tap%3 - 1; \
        int yy = yimg + dy; \
        uint32_t abuf = sb + ((IT)%3)*8192; \
        uint32_t bbuf = sb + 24576 + ((IT)%3)*16384; \
        for (int e = tid; e < 512; e += 256){ \
            int r = e >> 3, c = e & 7; \
            int xx = r + dx; \
            bool ok = (yy >= 0 && yy < HH && xx >= 0 && xx < WW); \
            int pix = bimg*HW + (ok ? (yy*WW + xx) : 0); \
            uint32_t sz = ok ? 16u : 0u; \
            uint32_t off = (uint32_t)(r*128 + c*16); \
            cp_async16z(abuf + SWZ(off), latbf + (size_t)pix*DM + kc + c*8, sz); \
        } \
        for (int e = tid; e < 1024; e += 256){ \
            int r = e >> 3, c = e & 7; \
            uint32_t off = (uint32_t)(r*128 + c*16); \
            cp_async16z(bbuf + SWZ(off), Wt + (size_t)(n0+r)*KP + kk + c*8, 16u); \
        } \
        asm volatile("cp.async.commit_group;" ::: "memory"); \
    } while(0)

    CSTAGE(0);
    CSTAGE(1);
    for (int it = 0; it < nit; it++){
        if (it < nit-1) asm volatile("cp.async.wait_group 1;" ::: "memory");
        else            asm volatile("cp.async.wait_group 0;" ::: "memory");
        __syncthreads();
        if (it + 2 < nit) CSTAGE(it+2);
        uint32_t abuf = sb + (it%3)*8192;
        uint32_t bbuf = sb + 24576 + (it%3)*16384;
        #pragma unroll
        for (int ks = 0; ks < 4; ks++){
            uint32_t afr[2][4], bfr[2][4];
            #pragma unroll
            for (int mi = 0; mi < 2; mi++){
                int row = warp_m*32 + mi*16 + (lane & 15);
                uint32_t off = (uint32_t)(row*128 + ks*32 + ((lane>>4)<<4));
                ldm_x4(afr[mi], abuf + SWZ(off));
            }
            #pragma unroll
            for (int p = 0; p < 2; p++){
                int row = warp_n*32 + p*16 + (lane & 15);
                uint32_t off = (uint32_t)(row*128 + ks*32 + ((lane>>4)<<4));
                ldm_x4(bfr[p], bbuf + SWZ(off));
            }
            #pragma unroll
            for (int mi = 0; mi < 2; mi++)
                #pragma unroll
                for (int ni = 0; ni < 4; ni++)
                    mma_bf16(acc[mi][ni], afr[mi],
                             bfr[ni>>1][ni&1], bfr[ni>>1][2 + (ni&1)]);
        }
    }
    #undef CSTAGE

    #pragma unroll
    for (int ni = 0; ni < 4; ni++){
        int col = n0 + warp_n*32 + ni*8 + (lane & 3)*2;
        float b0 = biasN[col], b1 = biasN[col+1];
        #pragma unroll
        for (int mi = 0; mi < 2; mi++){
            int rbase = m0 + warp_m*32 + mi*16 + (lane >> 2);
            #pragma unroll
            for (int h = 0; h < 2; h++){
                int row = rbase + h*8;
                long ci = (long)row*DM + col;
                outbf[ci]   = __float2bfloat16(acc[mi][ni][h*2+0] + b0);
                outbf[ci+1] = __float2bfloat16(acc[mi][ni][h*2+1] + b1);
            }
        }
    }
}

// ===================================================================================
// Fused attention: logits (qq @ kv^T)/16 + softmax -> attn_bf (padded KQ).
// grid (ceil(NQ/64), 1, BB), 256 threads.
// ===================================================================================
__global__ void __launch_bounds__(256) k_attn(){
    extern __shared__ __align__(128) char smem[];
    const uint32_t sb = smem_u32(smem);
    float* scores = (float*)(smem + 98304);
    const int tid = threadIdx.x;
    const int lane = tid & 31, wid = tid >> 5;
    const int warp_m = wid & 1;
    const int warp_n = wid >> 1;
    const int m0 = blockIdx.x * 64;
    const int b  = blockIdx.z;
    const bf16* Ap = g_qq_bf + (long)b*NQ*DM;
    const bf16* Bp = g_kv_bf + (long)b*NQ*DM;

    for (int e = tid; e < 2048; e += 256){
        int r = e >> 5, c = e & 31;
        int kb = c >> 3, cc = c & 7;
        int gm = m0 + r;
        uint32_t sz = gm < NQ ? 16u : 0u;
        int rm = gm < NQ ? gm : 0;
        uint32_t off = (uint32_t)(r*128 + cc*16);
        cp_async16z(sb + kb*8192 + SWZ(off), Ap + (size_t)rm*DM + kb*64 + cc*8, sz);
    }
    asm volatile("cp.async.commit_group;" ::: "memory");

    for (int nt = 0; nt < 3; nt++){
        for (int e = tid; e < 4096; e += 256){
            int r = e >> 5, c = e & 31;
            int kb = c >> 3, cc = c & 7;
            int gn = nt*128 + r;
            uint32_t sz = gn < NQ ? 16u : 0u;
            int rn = gn < NQ ? gn : 0;
            uint32_t off = (uint32_t)(r*128 + cc*16);
            cp_async16z(sb + 32768 + kb*16384 + SWZ(off), Bp + (size_t)rn*DM + kb*64 + cc*8, sz);
        }
        asm volatile("cp.async.commit_group;" ::: "memory");
        asm volatile("cp.async.wait_group 0;" ::: "memory");
        __syncthreads();

        float acc[2][4][4];
        #pragma unroll
        for (int mi=0;mi<2;mi++)
            #pragma unroll
            for (int ni=0;ni<4;ni++)
                #pragma unroll
                for (int c=0;c<4;c++) acc[mi][ni][c]=0.f;

        #pragma unroll
        for (int kb = 0; kb < 4; kb++){
            uint32_t abuf = sb + kb*8192;
            uint32_t bbuf = sb + 32768 + kb*16384;
            #pragma unroll
            for (int ks = 0; ks < 4; ks++){
                uint32_t afr[2][4], bfr[2][4];
                #pragma unroll
                for (int mi = 0; mi < 2; mi++){
                    int row = warp_m*32 + mi*16 + (lane & 15);
                    uint32_t off = (uint32_t)(row*128 + ks*32 + ((lane>>4)<<4));
                    ldm_x4(afr[mi], abuf + SWZ(off));
                }
                #pragma unroll
                for (int p = 0; p < 2; p++){
                    int row = warp_n*32 + p*16 + (lane & 15);
                    uint32_t off = (uint32_t)(row*128 + ks*32 + ((lane>>4)<<4));
                    ldm_x4(bfr[p], bbuf + SWZ(off));
                }
                #pragma unroll
                for (int mi = 0; mi < 2; mi++)
                    #pragma unroll
                    for (int ni = 0; ni < 4; ni++)
                        mma_bf16(acc[mi][ni], afr[mi],
                                 bfr[ni>>1][ni&1], bfr[ni>>1][2 + (ni&1)]);
            }
        }

        #pragma unroll
        for (int ni = 0; ni < 4; ni++){
            int col = nt*128 + warp_n*32 + ni*8 + (lane & 3)*2;
            if (col >= KQ) continue;
            #pragma unroll
            for (int mi = 0; mi < 2; mi++){
                int rbase = warp_m*32 + mi*16 + (lane >> 2);
                #pragma unroll
                for (int h = 0; h < 2; h++){
                    int row = rbase + h*8;
                    scores[row*KQ + col]     = acc[mi][ni][h*2+0] * 0.0625f;
                    scores[row*KQ + col + 1] = acc[mi][ni][h*2+1] * 0.0625f;
                }
            }
        }
        __syncthreads();
    }

    for (int rr = wid*8; rr < wid*8 + 8; rr++){
        int gq = m0 + rr;
        if (gq >= NQ) continue;
        float* srow = scores + rr*KQ;
        float m = -1e30f;
        for (int j = lane; j < NQ; j += 32) m = fmaxf(m, srow[j]);
        #pragma unroll
        for (int s = 16; s > 0; s >>= 1) m = fmaxf(m, __shfl_xor_sync(0xFFFFFFFF, m, s));
        float sum = 0.f;
        for (int j = lane; j < NQ; j += 32){ float e = expf(srow[j]-m); srow[j] = e; sum += e; }
        #pragma unroll
        for (int s = 16; s > 0; s >>= 1) sum += __shfl_xor_sync(0xFFFFFFFF, sum, s);
        float inv = 1.f / sum;
        bf16* orow = g_attn_bf + (long)(b*NQ + gq)*KQ;
        for (int j = lane; j < KQ; j += 32)
            orow[j] = __float2bfloat16(j < NQ ? srow[j]*inv : 0.f);
    }
}

// ===================================================================================
// Fused ao+Wo: queries += (attn @ kvt^T) @ Wo^T + bo.
// grid (5, 1, BB), 256 threads. smem: Astage 8KB @0, Bstage 32KB @8192, AO 32KB @40960.
// ===================================================================================
__global__ void __launch_bounds__(256) k_aowo(
    const bf16* __restrict__ Wo_l, const float* __restrict__ bo_l)
{
    extern __shared__ __align__(128) char smem[];
    const uint32_t sb = smem_u32(smem);
    const int tid = threadIdx.x;
    const int lane = tid & 31, wid = tid >> 5;
    const int warp_m = wid & 1;     // 2 x 32 rows
    const int warp_n = wid >> 1;    // 4 x 64 cols
    const int m0 = blockIdx.x * 64; // 0..256
    const int b  = blockIdx.z;

    float acc[2][8][4];
    #pragma unroll
    for (int mi=0;mi<2;mi++)
        #pragma unroll
        for (int ni=0;ni<8;ni++)
            #pragma unroll
            for (int c=0;c<4;c++) acc[mi][ni][c]=0.f;

    // ---- stage 1: ao = attn @ kvt^T (K = KQ = 320, 5 chunks) ----
    for (int kc = 0; kc < 5; kc++){
        if (kc) __syncthreads();
        for (int e = tid; e < 512; e += 256){
            int r = e >> 3, c = e & 7;
            int gm = m0 + r;
            uint32_t sz = gm < NQ ? 16u : 0u;
            int rm = gm < NQ ? gm : 0;
            cp_async16z(sb + SWZ((uint32_t)(r*128 + c*16)),
                        g_attn_bf + (size_t)(b*NQ + rm)*KQ + kc*64 + c*8, sz);
        }
        for (int e = tid; e < 2048; e += 256){
            int r = e >> 3, c = e & 7;
            cp_async16z(sb + 8192 + SWZ((uint32_t)(r*128 + c*16)),
                        g_kvt + (size_t)b*DM*KQ + (size_t)r*KQ + kc*64 + c*8, 16u);
        }
        asm volatile("cp.async.commit_group;" ::: "memory");
        asm volatile("cp.async.wait_group 0;" ::: "memory");
        __syncthreads();
        #pragma unroll
        for (int ks = 0; ks < 4; ks++){
            uint32_t afr[2][4], bfr[4][4];
            #pragma unroll
            for (int mi = 0; mi < 2; mi++){
                int row = warp_m*32 + mi*16 + (lane & 15);
                uint32_t off = (uint32_t)(row*128 + ks*32 + ((lane>>4)<<4));
                ldm_x4(afr[mi], sb + SWZ(off));
            }
            #pragma unroll
            for (int p = 0; p < 4; p++){
                int row = warp_n*64 + p*16 + (lane & 15);
                uint32_t off = (uint32_t)(row*128 + ks*32 + ((lane>>4)<<4));
                ldm_x4(bfr[p], sb + 8192 + SWZ(off));
            }
            #pragma unroll
            for (int mi = 0; mi < 2; mi++)
                #pragma unroll
                for (int ni = 0; ni < 8; ni++)
                    mma_bf16(acc[mi][ni], afr[mi],
                             bfr[ni>>1][ni&1], bfr[ni>>1][2 + (ni&1)]);
        }
    }

    // ---- write ao into smem (bf16, K-major chunks for GEMM2) ----
    __syncthreads();
    #pragma unroll
    for (int ni = 0; ni < 8; ni++){
        int col = warp_n*64 + ni*8 + (lane & 3)*2;
        #pragma unroll
        for (int mi = 0; mi < 2; mi++){
            int rbase = warp_m*32 + mi*16 + (lane >> 2);
            #pragma unroll
            for (int h = 0; h < 2; h++){
                int row = rbase + h*8;
                uint32_t off = (uint32_t)((col>>6)*8192) + SWZ((uint32_t)(row*128 + (col&63)*2));
                __nv_bfloat162 pk = __floats2bfloat162_rn(acc[mi][ni][h*2], acc[mi][ni][h*2+1]);
                *(__nv_bfloat162*)(smem + 40960 + off) = pk;
            }
        }
    }
    __syncthreads();

    // ---- stage 2: out = ao @ Wo^T (K = 256, 4 chunks) ----
    float acc2[2][8][4];
    #pragma unroll
    for (int mi=0;mi<2;mi++)
        #pragma unroll
        for (int ni=0;ni<8;ni++)
            #pragma unroll
            for (int c=0;c<4;c++) acc2[mi][ni][c]=0.f;

    for (int kc = 0; kc < 4; kc++){
        if (kc) __syncthreads();
        for (int e = tid; e < 2048; e += 256){
            int r = e >> 3, c = e & 7;
            cp_async16z(sb + 8192 + SWZ((uint32_t)(r*128 + c*16)),
                        Wo_l + (size_t)r*DM + kc*64 + c*8, 16u);
        }
        asm volatile("cp.async.commit_group;" ::: "memory");
        asm volatile("cp.async.wait_group 0;" ::: "memory");
        __syncthreads();
        #pragma unroll
        for (int ks = 0; ks < 4; ks++){
            uint32_t afr[2][4], bfr[4][4];
            #pragma unroll
            for (int mi = 0; mi < 2; mi++){
                int row = warp_m*32 + mi*16 + (lane & 15);
                uint32_t off = (uint32_t)(row*128 + ks*32 + ((lane>>4)<<4));
                ldm_x4(afr[mi], sb + 40960 + kc*8192 + SWZ(off));
            }
            #pragma unroll
            for (int p = 0; p < 4; p++){
                int row = warp_n*64 + p*16 + (lane & 15);
                uint32_t off = (uint32_t)(row*128 + ks*32 + ((lane>>4)<<4));
                ldm_x4(bfr[p], sb + 8192 + SWZ(off));
            }
            #pragma unroll
            for (int mi = 0; mi < 2; mi++)
                #pragma unroll
                for (int ni = 0; ni < 8; ni++)
                    mma_bf16(acc2[mi][ni], afr[mi],
                             bfr[ni>>1][ni&1], bfr[ni>>1][2 + (ni&1)]);
        }
    }

    // ---- epilogue: residual update ----
    #pragma unroll
    for (int ni = 0; ni < 8; ni++){
        int col = warp_n*64 + ni*8 + (lane & 3)*2;
        float b0 = bo_l[col], b1 = bo_l[col+1];
        #pragma unroll
        for (int mi = 0; mi < 2; mi++){
            int rbase = warp_m*32 + mi*16 + (lane >> 2);
            #pragma unroll
            for (int h = 0; h < 2; h++){
                int row = rbase + h*8;
                int grow = m0 + row;
                if (grow >= NQ) continue;
                size_t ci = (size_t)(b*NQ + grow)*DM + col;
                float v0 = acc2[mi][ni][h*2+0] + b0 + g_queries[ci];
                float v1 = acc2[mi][ni][h*2+1] + b1 + g_queries[ci+1];
                g_queries[ci]   = v0;
                g_queries[ci+1] = v1;
                g_q_bf[ci]   = __float2bfloat16(v0);
                g_q_bf[ci+1] = __float2bfloat16(v1);
            }
        }
    }
}

// ===================================================================================
// Fused sampler: h1 = relu(q@w_r1^T+b), ro=tanh(h1@w_r2^T+b)*0.5, ref, bilinear sample.
// ===================================================================================
__global__ void __launch_bounds__(256) k_sampler(
    const float* __restrict__ w_r2, const float* __restrict__ b_r2,
    const float* __restrict__ b_r1)
{
    __shared__ float q_s[DM];
    __shared__ float h1_s[DM];
    __shared__ float ref_s[16];
    int r = blockIdx.x;
    int b = r / NQ;
    int tid = threadIdx.x;
    int lane = tid & 31, wid = tid >> 5;

    q_s[tid] = __bfloat162float(g_q_bf[(long)r*DM + tid]);
    __syncthreads();

    float acc = b_r1[tid];
    #pragma unroll 8
    for (int k = 0; k < DM; k++)
        acc += q_s[k] * __bfloat162float(g_wr1T[(long)k*DM + tid]);
    h1_s[tid] = fmaxf(acc, 0.f);
    __syncthreads();

    #pragma unroll
    for (int jj = 0; jj < 2; jj++){
        int j = wid*2 + jj;
        float part = 0.f;
        for (int k = lane; k < DM; k += 32)
            part += h1_s[k] * w_r2[j*DM + k];
        #pragma unroll
        for (int s = 16; s > 0; s >>= 1) part += __shfl_xor_sync(0xFFFFFFFF, part, s);
        if (lane == 0){
            float ro = tanhf(part + b_r2[j]) * 0.5f;
            int c = j & 1;
            float v = g_boxes[r*4 + c] + ro;
            ref_s[j] = fminf(fmaxf(v, 0.f), 1.f);
        }
    }
    __syncthreads();

    int p  = tid >> 5;
    int cg = tid & 31;
    int rp = r*NP + p;
    float rx = ref_s[p*2+0], ry = ref_s[p*2+1];
    const bf16* f1 = g_f1bf + (long)b*HW*DM;
    float gx0 = rx*2.f - 1.f;
    float gy0 = ry*2.f - 1.f;
    #pragma unroll
    for (int t=0;t<9;t++){
        float ox = (float)(t%3 - 1), oy = (float)(t/3 - 1);
        float gx = gx0 + ox*(2.f/WW);
        float gy = gy0 + oy*(2.f/HH);
        float x = fminf(fmaxf((gx+1.f)*0.5f*(WW-1), 0.f), (float)(WW-1));
        float y = fminf(fmaxf((gy+1.f)*0.5f*(HH-1), 0.f), (float)(HH-1));
        float x0f = floorf(x), y0f = floorf(y);
        float wx = x - x0f, wy = y - y0f;
        int x0 = (int)x0f, y0 = (int)y0f;
        int x1 = min(x0+1, WW-1), y1 = min(y0+1, HH-1);
        float w00 = (1.f-wx)*(1.f-wy), w01 = wx*(1.f-wy);
        float w10 = (1.f-wx)*wy,       w11 = wx*wy;
        uint4 q00 = *((const uint4*)(f1 + ((long)y0*WW + x0)*DM) + cg);
        uint4 q01 = *((const uint4*)(f1 + ((long)y0*WW + x1)*DM) + cg);
        uint4 q10 = *((const uint4*)(f1 + ((long)y1*WW + x0)*DM) + cg);
        uint4 q11 = *((const uint4*)(f1 + ((long)y1*WW + x1)*DM) + cg);
        const uint32_t* a00 = (const uint32_t*)&q00;
        const uint32_t* a01 = (const uint32_t*)&q01;
        const uint32_t* a10 = (const uint32_t*)&q10;
        const uint32_t* a11 = (const uint32_t*)&q11;
        uint4 o;
        uint32_t* o32 = (uint32_t*)&o;
        #pragma unroll
        for (int j = 0; j < 4; j++){
            float2 f00 = __bfloat1622float2(*(const __nv_bfloat162*)&a00[j]);
            float2 f01 = __bfloat1622float2(*(const __nv_bfloat162*)&a01[j]);
            float2 f10 = __bfloat1622float2(*(const __nv_bfloat162*)&a10[j]);
            float2 f11 = __bfloat1622float2(*(const __nv_bfloat162*)&a11[j]);
            float vx = f00.x*w00 + f01.x*w01 + f10.x*w10 + f11.x*w11;
            float vy = f00.y*w00 + f01.y*w01 + f10.y*w10 + f11.y*w11;
            __nv_bfloat162 pk = __floats2bfloat162_rn(vx, vy);
            o32[j] = *(uint32_t*)&pk;
        }
        *((uint4*)(g_sampled_bf + (long)rp*KP + t*DM) + cg) = o;
    }
}

// ===================================================================================
// Fused box head.
// ===================================================================================
__global__ void __launch_bounds__(256) k_boxhead(
    const float* __restrict__ w_b2, const float* __restrict__ b_b2,
    const float* __restrict__ b_b1)
{
    __shared__ float q_s[DM];
    __shared__ float hb_s[DM];
    int r = blockIdx.x;
    int tid = threadIdx.x;
    int lane = tid & 31, wid = tid >> 5;

    q_s[tid] = __bfloat162float(g_q_bf[(long)r*DM + tid]);
    __syncthreads();

    float acc = b_b1[tid];
    #pragma unroll 8
    for (int k = 0; k < DM; k++)
        acc += q_s[k] * __bfloat162float(g_wb1T[(long)k*DM + tid]);
    hb_s[tid] = fmaxf(acc, 0.f);
    __syncthreads();

    if (wid < 4){
        int j = wid;
        float part = 0.f;
        for (int k = lane; k < DM; k += 32)
            part += hb_s[k] * w_b2[j*DM + k];
        #pragma unroll
        for (int s = 16; s > 0; s >>= 1) part += __shfl_xor_sync(0xFFFFFFFF, part, s);
        if (lane == 0){
            float delta = 1.f/(1.f + expf(-(part + b_b2[j])));
            float v = g_boxes[r*4 + j] + 0.1f*tanhf(delta - 0.5f);
            g_boxes[r*4 + j] = fminf(fmaxf(v, 0.f), 1.f);
        }
    }
}

// ----------------------------- small kernels -----------------------------
__global__ void k_cast4(const float* __restrict__ s, bf16* __restrict__ d, int n4){
    int i = blockIdx.x*256 + threadIdx.x;
    if (i >= n4) return;
    float4 v = ((const float4*)s)[i];
    __nv_bfloat162 lo = __floats2bfloat162_rn(v.x, v.y);
    __nv_bfloat162 hi = __floats2bfloat162_rn(v.z, v.w);
    ((__nv_bfloat162*)d)[i*2]   = lo;
    ((__nv_bfloat162*)d)[i*2+1] = hi;
}

#define S1 (DM*DM)
__global__ void k_prep_small(const float* __restrict__ w_lat, const float* __restrict__ w_r1,
                             const float* __restrict__ w_b1, const float* __restrict__ Wq,
                             const float* __restrict__ Wo, const float* __restrict__ Wp2){
    int idx = blockIdx.x*256 + threadIdx.x;
    if (idx < S1){
        g_wlat_bf[idx] = __float2bfloat16(w_lat[idx]);
    } else if (idx < 2*S1){
        int i = idx - S1;
        int k = i / DM, o = i % DM;
        g_wr1T[i] = __float2bfloat16(w_r1[o*DM + k]);
    } else if (idx < 3*S1){
        int i = idx - 2*S1;
        int k = i / DM, o = i % DM;
        g_wb1T[i] = __float2bfloat16(w_b1[o*DM + k]);
    } else if (idx < (3+NL)*S1){
        int i = idx - 3*S1;
        g_Wq_bf[i] = __float2bfloat16(Wq[i]);
    } else if (idx < (3+2*NL)*S1){
        int i = idx - (3+NL)*S1;
        g_Wo_bf[i] = __float2bfloat16(Wo[i]);
    } else if (idx < (3+3*NL)*S1){
        int i = idx - (3+2*NL)*S1;
        g_Wp2_bf[i] = __float2bfloat16(Wp2[i]);
    }
}

__global__ void k_fuse_w(const float* __restrict__ w_tf, const float* __restrict__ b_tf,
                         const float* __restrict__ w_in, const float* __restrict__ b_in)
{
    int d = blockIdx.x;
    int t = threadIdx.x;   // 128
    __shared__ float win_s[CIN];
    __shared__ float red[CIN];
    win_s[t] = w_in[d*CIN + t];
    __syncthreads();
    int i = t;
    for (int kd=0; kd<3; kd++){
        float acc = 0.f;
        for (int o=0;o<CIN;o++) acc += win_s[o]*w_tf[(o*CIN + i)*3 + kd];
        g_Wf_bf[d*K3 + kd*CIN + i] = __float2bfloat16(acc * (1.0f/TT));
    }
    red[t] = win_s[t]*b_tf[t];
    __syncthreads();
    for (int s=64;s>0;s>>=1){ if (t<s) red[t]+=red[t+s]; __syncthreads(); }
    if (t==0) g_bfv[d] = b_in[d] + red[0];
}

__global__ void k_wsm_flat(const float* __restrict__ w_sm){
    int idx = blockIdx.x*256 + threadIdx.x;
    if (idx >= DM*KP) return;
    int o = idx / KP;
    int r = idx % KP;
    int t = r / DM, c = r % DM;
    g_wsm_bf[idx] = __float2bfloat16(w_sm[((long)o*DM + c)*9 + t]);
}

__global__ void k_tsum(const float* __restrict__ feat){
    int idx = blockIdx.x*256 + threadIdx.x;
    if (idx >= BB*CIN*HW) return;
    int p = idx % HW;
    int i = (idx/HW) % CIN;
    int b = idx/(HW*CIN);
    const float* f = feat + (((long)b*TT)*CIN + i)*HW + p;
    const long st = (long)CIN*HW;
    float v0=f[0], v1=f[st], v2=f[2*st], v3=f[3*st];
    float s = v0+v1+v2+v3;
    bf16* o = g_St + ((long)b*HW + p)*K3 + i;
    o[0*CIN] = __float2bfloat16(s - v3);
    o[1*CIN] = __float2bfloat16(s);
    o[2*CIN] = __float2bfloat16(s - v0);
}

__global__ void k_init(const float* __restrict__ q_embed, const float* __restrict__ q_pos,
                       const float* __restrict__ boxes0){
    int idx = blockIdx.x*256 + threadIdx.x;
    if (idx < ROWS*DM){
        int qd = idx % (NQ*DM);
        float v = q_embed[qd] + q_pos[qd];
        g_queries[idx] = v;
        g_q_bf[idx] = __float2bfloat16(v);
    }
    if (idx < ROWS*4) g_boxes[idx] = boxes0[idx];
    if (idx < BB*DM*KQ) g_kvt[idx] = __float2bfloat16(0.f);
}

__global__ void k_final(const float* __restrict__ w_cls, const float* __restrict__ b_cls,
                        float* __restrict__ out){
    int idx = blockIdx.x*256 + threadIdx.x;
    if (idx >= ROWS + ROWS*4) return;
    if (idx < ROWS){
        const float* q = g_queries + (long)idx*DM;
        float acc = 0.f;
        for (int k=0;k<DM;k++) acc += q[k]*w_cls[k];
        out[idx] = acc + b_cls[0];
    } else {
        out[idx] = g_boxes[idx - ROWS];
    }
}

// ----------------------------- launcher -----------------------------
static inline int ceil_div(int a, int b){ return (a+b-1)/b; }

extern "C" void kernel_launch(void* const* d_in, const int* in_sizes, int n_in,
                              void* d_out, int out_size)
{
    const float* feat    = (const float*)d_in[0];
    const float* boxes0  = (const float*)d_in[1];
    const float* w_tf    = (const float*)d_in[2];
    const float* b_tf    = (const float*)d_in[3];
    const float* w_in    = (const float*)d_in[4];
    const float* b_in    = (const float*)d_in[5];
    const float* w_lat   = (const float*)d_in[6];
    const float* b_lat   = (const float*)d_in[7];
    const float* w_sm    = (const float*)d_in[8];
    const float* b_sm    = (const float*)d_in[9];
    const float* q_embed = (const float*)d_in[10];
    const float* q_pos   = (const float*)d_in[11];
    const float* Wq      = (const float*)d_in[12];
    const float* bq      = (const float*)d_in[13];
    const float* Wo      = (const float*)d_in[14];
    const float* bo      = (const float*)d_in[15];
    const float* Wp1     = (const float*)d_in[16];
    const float* bp1     = (const float*)d_in[17];
    const float* Wp2     = (const float*)d_in[18];
    const float* bp2     = (const float*)d_in[19];
    const float* w_r1    = (const float*)d_in[20];
    const float* b_r1    = (const float*)d_in[21];
    const float* w_r2    = (const float*)d_in[22];
    const float* b_r2    = (const float*)d_in[23];
    const float* w_b1    = (const float*)d_in[24];
    const float* b_b1    = (const float*)d_in[25];
    const float* w_b2    = (const float*)d_in[26];
    const float* b_b2    = (const float*)d_in[27];
    const float* w_cls   = (const float*)d_in[28];
    const float* b_cls   = (const float*)d_in[29];
    float* out = (float*)d_out;

    cudaFuncSetAttribute(k_hmma, cudaFuncAttributeMaxDynamicSharedMemorySize, SMEM_DYN);
    cudaFuncSetAttribute(k_conv_hmma, cudaFuncAttributeMaxDynamicSharedMemorySize, SMEM_DYN);
    cudaFuncSetAttribute(k_attn, cudaFuncAttributeMaxDynamicSharedMemorySize, ATTN_SMEM);
    cudaFuncSetAttribute(k_aowo, cudaFuncAttributeMaxDynamicSharedMemorySize, SMEM_DYN);

    float *pbfv, *pq;
    bf16 *pSt, *pWfb, *pxbf, *platbf, *pf1bf, *pwsmb, *pwlatb;
    bf16 *pWqb, *pWob, *pWp2b, *pWp1b, *pqbf, *psamp, *ppvmb, *pkvb, *pkvt, *pqqb, *pattnb;
    cudaGetSymbolAddress((void**)&pSt,    g_St);
    cudaGetSymbolAddress((void**)&pWfb,   g_Wf_bf);
    cudaGetSymbolAddress((void**)&pbfv,   g_bfv);
    cudaGetSymbolAddress((void**)&pxbf,   g_xbf);
    cudaGetSymbolAddress((void**)&platbf, g_latbf);
    cudaGetSymbolAddress((void**)&pf1bf,  g_f1bf);
    cudaGetSymbolAddress((void**)&pwsmb,  g_wsm_bf);
    cudaGetSymbolAddress((void**)&pwlatb, g_wlat_bf);
    cudaGetSymbolAddress((void**)&pWqb,   g_Wq_bf);
    cudaGetSymbolAddress((void**)&pWob,   g_Wo_bf);
    cudaGetSymbolAddress((void**)&pWp2b,  g_Wp2_bf);
    cudaGetSymbolAddress((void**)&pWp1b,  g_Wp1_bf);
    cudaGetSymbolAddress((void**)&pq,     g_queries);
    cudaGetSymbolAddress((void**)&pqbf,   g_q_bf);
    cudaGetSymbolAddress((void**)&psamp,  g_sampled_bf);
    cudaGetSymbolAddress((void**)&ppvmb,  g_pvm_bf);
    cudaGetSymbolAddress((void**)&pkvb,   g_kv_bf);
    cudaGetSymbolAddress((void**)&pkvt,   g_kvt);
    cudaGetSymbolAddress((void**)&pqqb,   g_qq_bf);
    cudaGetSymbolAddress((void**)&pattnb, g_attn_bf);

    // ---------------- prologue ----------------
    k_fuse_w<<<DM, CIN>>>(w_tf, b_tf, w_in, b_in);
    k_wsm_flat<<<ceil_div(DM*KP,256), 256>>>(w_sm);
    k_prep_small<<<ceil_div((3+3*NL)*S1,256), 256>>>(w_lat, w_r1, w_b1, Wq, Wo, Wp2);
    k_cast4<<<ceil_div(NL*DM*KP/4,256),256>>>(Wp1, pWp1b, NL*DM*KP/4);
    k_tsum<<<ceil_div(BB*CIN*HW,256), 256>>>(feat);

    // ---------------- backbone ----------------
    k_hmma<<<dim3(HW/64, DM/128, BB), 256, SMEM_DYN>>>(
        pSt, pWfb, pbfv, nullptr, nullptr, pxbf, nullptr, nullptr,
        HW, DM, K3, K3, K3, DM,
        (long)HW*K3, 0, (long)HW*DM, 0, 1.0f, 1);

    k_hmma<<<dim3(HW/64, DM/128, BB), 256, SMEM_DYN>>>(
        pxbf, pwlatb, b_lat, nullptr, nullptr, platbf, nullptr, nullptr,
        HW, DM, DM, DM, DM, DM,
        (long)HW*DM, 0, (long)HW*DM, 0, 1.0f, 0);

    k_conv_hmma<<<dim3(BB*HW/64, DM/128), 256, SMEM_DYN>>>(platbf, pwsmb, b_sm, pf1bf);

    k_init<<<ceil_div(BB*DM*KQ,256), 256>>>(q_embed, q_pos, boxes0);

    // ---------------- decoder ----------------
    for (int l=0; l<NL; l++){
        const float* bq_l  = bq  + (long)l*DM;
        const float* bo_l  = bo  + (long)l*DM;
        const float* bp1_l = bp1 + (long)l*DM;
        const float* bp2_l = bp2 + (long)l*DM;
        bf16* Wq_l  = pWqb  + (long)l*DM*DM;
        bf16* Wo_l  = pWob  + (long)l*DM*DM;
        bf16* Wp2_l = pWp2b + (long)l*DM*DM;
        bf16* Wp1_l = pWp1b + (long)l*DM*KP;

        // qq = q_bf @ Wq^T + bq -> bf16
        k_hmma<<<dim3(ceil_div(ROWS,64), DM/128, 1), 256, SMEM_DYN>>>(
            pqbf, Wq_l, bq_l, nullptr, nullptr, pqqb, nullptr, nullptr,
            ROWS, DM, DM, DM, DM, DM, 0,0,0, 0, 1.0f, 0);

        // fused h1 + ref + sample
        k_sampler<<<ROWS, 256>>>(w_r2, b_r2, b_r1);

        // pv = relu(sampled @ Wp1^T + bp1), fused mean over NP -> pvm
        k_hmma<<<dim3(RP/64, DM/128, 1), 256, SMEM_DYN>>>(
            psamp, Wp1_l, bp1_l, nullptr, nullptr, nullptr, nullptr, ppvmb,
            RP, DM, KP, KP, KP, DM, 0,0,0, 1, 1.0f, 0);

        // kv = pvm @ Wp2^T + bp2 -> bf16 (+ transposed)
        k_hmma<<<dim3(ceil_div(ROWS,64), DM/128, 1), 256, SMEM_DYN>>>(
            ppvmb, Wp2_l, bp2_l, nullptr, nullptr, pkvb, pkvt, nullptr,
            ROWS, DM, DM, DM, DM, DM, 0,0,0, 0, 1.0f, 0);

        // fused logits + softmax -> attn_bf
        k_attn<<<dim3(ceil_div(NQ,64), 1, BB), 256, ATTN_SMEM>>>();

        // fused (attn @ kvt) @ Wo + residual
        k_aowo<<<dim3(5, 1, BB), 256, SMEM_DYN>>>(Wo_l, bo_l);

        // fused hb + box update
        k_boxhead<<<ROWS, 256>>>(w_b2, b_b2, b_b1);
    }

    k_final<<<ceil_div(ROWS*5,256), 256>>>(w_cls, b_cls, out);
}